// round 3
// baseline (speedup 1.0000x reference)
#include <cuda_runtime.h>

// Problem constants (fixed by the reference)
#define NPTS 1048576          // N, power of two (2^20)
#define HW   300              // X = Y = Z = 300
#define NC   16               // channels
#define PLANE_CELLS (HW * HW)           // 90000
#define PLANE_ELEMS (PLANE_CELLS * NC)  // 1,440,000 floats = 5.76 MB per plane

// Channel-last scratch: planes as (h, w, c), lines as (x, c).
// Order: planes[0]=xy, [1]=yz, [2]=xz ; lines[0]=x, [1]=y, [2]=z
__device__ __align__(16) float g_planes[3][PLANE_ELEMS];   // 17.3 MB total
__device__ __align__(16) float g_lines[3][HW * NC];        // 57.6 KB total

// ---------------------------------------------------------------------------
// Transpose (C,H,W) -> (H*W, C). One thread per (plane, cell); reads are
// coalesced along w per channel pass, writes are 64 B contiguous per thread.
// ---------------------------------------------------------------------------
__global__ __launch_bounds__(256) void transpose_planes(
    const float* __restrict__ p_xy,
    const float* __restrict__ p_yz,
    const float* __restrict__ p_xz)
{
    int tid = blockIdx.x * blockDim.x + threadIdx.x;
    if (tid >= 3 * PLANE_CELLS) return;
    int p    = tid / PLANE_CELLS;
    int cell = tid - p * PLANE_CELLS;
    const float* __restrict__ src = (p == 0) ? p_xy : (p == 1) ? p_yz : p_xz;
    float4* dst = reinterpret_cast<float4*>(g_planes[p] + cell * NC);
#pragma unroll
    for (int cc = 0; cc < 4; cc++) {
        float4 v;
        v.x = src[(cc * 4 + 0) * PLANE_CELLS + cell];
        v.y = src[(cc * 4 + 1) * PLANE_CELLS + cell];
        v.z = src[(cc * 4 + 2) * PLANE_CELLS + cell];
        v.w = src[(cc * 4 + 3) * PLANE_CELLS + cell];
        dst[cc] = v;
    }
}

__global__ __launch_bounds__(256) void transpose_lines(
    const float* __restrict__ l_x,
    const float* __restrict__ l_y,
    const float* __restrict__ l_z)
{
    int tid = blockIdx.x * blockDim.x + threadIdx.x;
    if (tid >= 3 * HW) return;
    int l = tid / HW;
    int x = tid - l * HW;
    const float* __restrict__ src = (l == 0) ? l_x : (l == 1) ? l_y : l_z;
    float4* dst = reinterpret_cast<float4*>(g_lines[l] + x * NC);
#pragma unroll
    for (int cc = 0; cc < 4; cc++) {
        float4 v;
        v.x = src[(cc * 4 + 0) * HW + x];
        v.y = src[(cc * 4 + 1) * HW + x];
        v.z = src[(cc * 4 + 2) * HW + x];
        v.w = src[(cc * 4 + 3) * HW + x];
        dst[cc] = v;
    }
}

// ---------------------------------------------------------------------------
// Main gather: one thread per (output slot, point).
//   slot 0: out_x = bilerp(plane_yz, cp[1]) * lerp(line_x, cl[0].y)
//   slot 1: out_y = bilerp(plane_xz, cp[2]) * lerp(line_y, cl[1].y)
//   slot 2: out_z = bilerp(plane_xy, cp[0]) * lerp(line_z, cl[2].y)
// Lines have W=1 in the reference => wx=0, pure 1-D lerp along the y coord.
// ---------------------------------------------------------------------------
__global__ __launch_bounds__(256) void sample_kernel(
    const float2* __restrict__ cp,   // coords_plane, (3, N) float2
    const float2* __restrict__ cl,   // coords_line,  (3, N) float2
    float*        __restrict__ out)  // (3, N, 16)
{
    unsigned tid = blockIdx.x * blockDim.x + threadIdx.x;
    if (tid >= 3u * NPTS) return;
    int slot = tid >> 20;            // NPTS = 2^20
    int n    = tid & (NPTS - 1);

    // slot -> which transposed plane / which cp row (line idx == slot)
    const int plane_of_slot[3] = {1, 2, 0};   // yz, xz, xy
    const int cp_of_slot[3]    = {1, 2, 0};
    int pi = plane_of_slot[slot];

    float2 pc = cp[cp_of_slot[slot] * NPTS + n];
    float2 lc = cl[slot * NPTS + n];

    // --- plane bilinear coords ---
    float ix = (pc.x + 1.0f) * 0.5f * (float)(HW - 1);
    float iy = (pc.y + 1.0f) * 0.5f * (float)(HW - 1);
    float ix0f = floorf(ix), iy0f = floorf(iy);
    float wx = ix - ix0f;
    float wy = iy - iy0f;
    int ix0 = min(max((int)ix0f, 0), HW - 1);
    int ix1 = min(ix0 + 1, HW - 1);
    int iy0 = min(max((int)iy0f, 0), HW - 1);
    int iy1 = min(iy0 + 1, HW - 1);

    float w00 = (1.0f - wx) * (1.0f - wy);
    float w01 = wx * (1.0f - wy);
    float w10 = (1.0f - wx) * wy;
    float w11 = wx * wy;

    const float4* __restrict__ row0 =
        reinterpret_cast<const float4*>(g_planes[pi] + iy0 * HW * NC);
    const float4* __restrict__ row1 =
        reinterpret_cast<const float4*>(g_planes[pi] + iy1 * HW * NC);
    int o0 = ix0 * 4;   // float4 index of channel block at x0
    int o1 = ix1 * 4;

    // --- line linear coords (W=1 => only the y component matters) ---
    float ly = (lc.y + 1.0f) * 0.5f * (float)(HW - 1);
    float ly0f = floorf(ly);
    float wly = ly - ly0f;
    int l0 = min(max((int)ly0f, 0), HW - 1);
    int l1 = min(l0 + 1, HW - 1);
    float lw0 = 1.0f - wly;

    const float4* __restrict__ L0 =
        reinterpret_cast<const float4*>(g_lines[slot] + l0 * NC);
    const float4* __restrict__ L1 =
        reinterpret_cast<const float4*>(g_lines[slot] + l1 * NC);

    float4* __restrict__ op =
        reinterpret_cast<float4*>(out + (size_t)slot * NPTS * NC + (size_t)n * NC);

#pragma unroll
    for (int cc = 0; cc < 4; cc++) {
        float4 v00 = row0[o0 + cc];
        float4 v01 = row0[o1 + cc];
        float4 v10 = row1[o0 + cc];
        float4 v11 = row1[o1 + cc];
        float4 a0  = L0[cc];
        float4 a1  = L1[cc];
        float4 r;
        r.x = (v00.x * w00 + v01.x * w01 + v10.x * w10 + v11.x * w11)
              * (a0.x * lw0 + a1.x * wly);
        r.y = (v00.y * w00 + v01.y * w01 + v10.y * w10 + v11.y * w11)
              * (a0.y * lw0 + a1.y * wly);
        r.z = (v00.z * w00 + v01.z * w01 + v10.z * w10 + v11.z * w11)
              * (a0.z * lw0 + a1.z * wly);
        r.w = (v00.w * w00 + v01.w * w01 + v10.w * w10 + v11.w * w11)
              * (a0.w * lw0 + a1.w * wly);
        op[cc] = r;
    }
}

// ---------------------------------------------------------------------------
// Inputs (metadata order = reference signature order):
//   0: coords_plane (3,1,N,1,2) f32
//   1: coords_line  (3,1,N,1,2) f32
//   2: plane_xy (1,16,300,300)  3: plane_yz  4: plane_xz
//   5: line_x  (1,16,300,1)     6: line_y    7: line_z
// Output: concat(out_x, out_y, out_z), each (N,16) f32.
// ---------------------------------------------------------------------------
extern "C" void kernel_launch(void* const* d_in, const int* in_sizes, int n_in,
                              void* d_out, int out_size)
{
    (void)in_sizes; (void)n_in; (void)out_size;

    const float* p_xy = (const float*)d_in[2];
    const float* p_yz = (const float*)d_in[3];
    const float* p_xz = (const float*)d_in[4];
    const float* l_x  = (const float*)d_in[5];
    const float* l_y  = (const float*)d_in[6];
    const float* l_z  = (const float*)d_in[7];

    transpose_planes<<<(3 * PLANE_CELLS + 255) / 256, 256>>>(p_xy, p_yz, p_xz);
    transpose_lines<<<(3 * HW + 255) / 256, 256>>>(l_x, l_y, l_z);

    sample_kernel<<<(3u * NPTS) / 256, 256>>>(
        (const float2*)d_in[0], (const float2*)d_in[1], (float*)d_out);
}

// round 4
// speedup vs baseline: 2.6032x; 2.6032x over previous
#include <cuda_runtime.h>

// Problem constants (fixed by the reference)
#define NPTS 1048576          // N = 2^20
#define HW   300              // X = Y = Z = 300
#define NC   16               // channels
#define PLANE_CELLS (HW * HW)           // 90000
#define PLANE_ELEMS (PLANE_CELLS * NC)  // 1,440,000 floats = 5.76 MB per plane

// Channel-last scratch: planes as (h, w, c), lines as (pos, c).
// planes[0]=xy, [1]=yz, [2]=xz ; lines[0]=x, [1]=y, [2]=z
__device__ __align__(16) float g_planes[3][PLANE_ELEMS];   // 17.3 MB
__device__ __align__(16) float g_lines[3][HW * NC];        // 57.6 KB

// ---------------------------------------------------------------------------
// Transpose (C,H,W) -> (H*W, C).
// ---------------------------------------------------------------------------
__global__ __launch_bounds__(256) void transpose_planes(
    const float* __restrict__ p_xy,
    const float* __restrict__ p_yz,
    const float* __restrict__ p_xz)
{
    int tid = blockIdx.x * blockDim.x + threadIdx.x;
    if (tid >= 3 * PLANE_CELLS) return;
    int p    = tid / PLANE_CELLS;
    int cell = tid - p * PLANE_CELLS;
    const float* __restrict__ src = (p == 0) ? p_xy : (p == 1) ? p_yz : p_xz;
    float4* dst = reinterpret_cast<float4*>(g_planes[p] + cell * NC);
#pragma unroll
    for (int cc = 0; cc < 4; cc++) {
        float4 v;
        v.x = src[(cc * 4 + 0) * PLANE_CELLS + cell];
        v.y = src[(cc * 4 + 1) * PLANE_CELLS + cell];
        v.z = src[(cc * 4 + 2) * PLANE_CELLS + cell];
        v.w = src[(cc * 4 + 3) * PLANE_CELLS + cell];
        dst[cc] = v;
    }
}

__global__ __launch_bounds__(256) void transpose_lines(
    const float* __restrict__ l_x,
    const float* __restrict__ l_y,
    const float* __restrict__ l_z)
{
    int tid = blockIdx.x * blockDim.x + threadIdx.x;
    if (tid >= 3 * HW) return;
    int l = tid / HW;
    int x = tid - l * HW;
    const float* __restrict__ src = (l == 0) ? l_x : (l == 1) ? l_y : l_z;
    float4* dst = reinterpret_cast<float4*>(g_lines[l] + x * NC);
#pragma unroll
    for (int cc = 0; cc < 4; cc++) {
        float4 v;
        v.x = src[(cc * 4 + 0) * HW + x];
        v.y = src[(cc * 4 + 1) * HW + x];
        v.z = src[(cc * 4 + 2) * HW + x];
        v.w = src[(cc * 4 + 3) * HW + x];
        dst[cc] = v;
    }
}

// ---------------------------------------------------------------------------
// Main gather, cooperative 4-lane teams: 4 consecutive lanes = one (slot, n),
// lane owns channel group c = tid & 3 (one float4 of the 64 B channel block).
// Every plane-corner / line-tap load is a contiguous 64 B quad access
// => 1 L1tex wavefront per corner per point (was 4).
//   slot 0: out_x = bilerp(plane_yz, cp[1]) * lerp(line_x, cl[0].y)
//   slot 1: out_y = bilerp(plane_xz, cp[2]) * lerp(line_y, cl[1].y)
//   slot 2: out_z = bilerp(plane_xy, cp[0]) * lerp(line_z, cl[2].y)
// ---------------------------------------------------------------------------
__global__ __launch_bounds__(256) void sample_kernel(
    const float2* __restrict__ cp,   // coords_plane, (3, N) float2
    const float2* __restrict__ cl,   // coords_line,  (3, N) float2
    float*        __restrict__ out)  // (3, N, 16)
{
    unsigned tid = blockIdx.x * blockDim.x + threadIdx.x;  // 3 * N * 4 threads
    int c    = tid & 3;                  // channel group (float4 index)
    int n    = (tid >> 2) & (NPTS - 1);  // point index
    int slot = tid >> 22;                // output slot 0..2

    // slot -> transposed plane index / cp row (line idx == slot)
    int pi = (slot == 0) ? 1 : (slot == 1) ? 2 : 0;

    // Warp's 8 consecutive points -> one 64 B line per coord array.
    float2 pc = cp[pi * NPTS + n];       // cp row == plane index mapping
    float2 lc = cl[slot * NPTS + n];

    // --- plane bilinear coords (redundant per quad; FMA is cheap) ---
    float ix = (pc.x + 1.0f) * 0.5f * (float)(HW - 1);
    float iy = (pc.y + 1.0f) * 0.5f * (float)(HW - 1);
    float ix0f = floorf(ix), iy0f = floorf(iy);
    float wx = ix - ix0f;
    float wy = iy - iy0f;
    int ix0 = min(max((int)ix0f, 0), HW - 1);
    int ix1 = min(ix0 + 1, HW - 1);
    int iy0 = min(max((int)iy0f, 0), HW - 1);
    int iy1 = min(iy0 + 1, HW - 1);

    float w00 = (1.0f - wx) * (1.0f - wy);
    float w01 = wx * (1.0f - wy);
    float w10 = (1.0f - wx) * wy;
    float w11 = wx * wy;

    const float* __restrict__ P = g_planes[pi];
    int r0 = iy0 * (HW * NC);
    int r1 = iy1 * (HW * NC);
    int c4 = c * 4;

    float4 v00 = *reinterpret_cast<const float4*>(P + r0 + ix0 * NC + c4);
    float4 v01 = *reinterpret_cast<const float4*>(P + r0 + ix1 * NC + c4);
    float4 v10 = *reinterpret_cast<const float4*>(P + r1 + ix0 * NC + c4);
    float4 v11 = *reinterpret_cast<const float4*>(P + r1 + ix1 * NC + c4);

    // --- line linear coords (W=1 => only the y component matters) ---
    float ly = (lc.y + 1.0f) * 0.5f * (float)(HW - 1);
    float ly0f = floorf(ly);
    float wly = ly - ly0f;
    int l0 = min(max((int)ly0f, 0), HW - 1);
    int l1 = min(l0 + 1, HW - 1);
    float lw0 = 1.0f - wly;

    const float* __restrict__ L = g_lines[slot];
    float4 a0 = *reinterpret_cast<const float4*>(L + l0 * NC + c4);
    float4 a1 = *reinterpret_cast<const float4*>(L + l1 * NC + c4);

    float4 r;
    r.x = (v00.x * w00 + v01.x * w01 + v10.x * w10 + v11.x * w11)
          * (a0.x * lw0 + a1.x * wly);
    r.y = (v00.y * w00 + v01.y * w01 + v10.y * w10 + v11.y * w11)
          * (a0.y * lw0 + a1.y * wly);
    r.z = (v00.z * w00 + v01.z * w01 + v10.z * w10 + v11.z * w11)
          * (a0.z * lw0 + a1.z * wly);
    r.w = (v00.w * w00 + v01.w * w01 + v10.w * w10 + v11.w * w11)
          * (a0.w * lw0 + a1.w * wly);

    // Warp stores 8 points * 64 B = 512 B fully coalesced.
    *reinterpret_cast<float4*>(out + (size_t)slot * NPTS * NC
                                   + (size_t)n * NC + c4) = r;
}

// ---------------------------------------------------------------------------
// Inputs (metadata order):
//   0: coords_plane (3,1,N,1,2)  1: coords_line (3,1,N,1,2)
//   2: plane_xy  3: plane_yz  4: plane_xz
//   5: line_x    6: line_y    7: line_z
// Output: concat(out_x, out_y, out_z), each (N,16) f32.
// ---------------------------------------------------------------------------
extern "C" void kernel_launch(void* const* d_in, const int* in_sizes, int n_in,
                              void* d_out, int out_size)
{
    (void)in_sizes; (void)n_in; (void)out_size;

    transpose_planes<<<(3 * PLANE_CELLS + 255) / 256, 256>>>(
        (const float*)d_in[2], (const float*)d_in[3], (const float*)d_in[4]);
    transpose_lines<<<(3 * HW + 255) / 256, 256>>>(
        (const float*)d_in[5], (const float*)d_in[6], (const float*)d_in[7]);

    // 3 slots * N points * 4 lanes/point
    sample_kernel<<<(3u * NPTS * 4u) / 256, 256>>>(
        (const float2*)d_in[0], (const float2*)d_in[1], (float*)d_out);
}

// round 6
// speedup vs baseline: 2.7995x; 1.0754x over previous
#include <cuda_runtime.h>
#include <cuda_fp16.h>

// Problem constants (fixed by the reference)
#define NPTS 1048576          // N = 2^20
#define HW   300              // X = Y = Z = 300
#define NC   16               // channels
#define PLANE_CELLS (HW * HW)           // 90000
#define PLANE_ELEMS (PLANE_CELLS * NC)  // 1,440,000 elems

// Channel-last scratch. Planes quantized to fp16 (math stays fp32):
// a cell's 16 channels = 32 B contiguous => 1 L2 sector per corner access.
// planes[0]=xy, [1]=yz, [2]=xz ; lines[0]=x, [1]=y, [2]=z (lines stay fp32).
__device__ __align__(16) __half g_planes[3][PLANE_ELEMS];  // 8.64 MB
__device__ __align__(16) float  g_lines[3][HW * NC];       // 57.6 KB

// ---------------------------------------------------------------------------
// Transpose (C,H,W) f32 -> (H*W, C) f16. Reads coalesced per channel pass,
// each thread writes one 32 B channel block (2x uint4).
// ---------------------------------------------------------------------------
__global__ __launch_bounds__(256) void transpose_planes(
    const float* __restrict__ p_xy,
    const float* __restrict__ p_yz,
    const float* __restrict__ p_xz)
{
    int tid = blockIdx.x * blockDim.x + threadIdx.x;
    if (tid >= 3 * PLANE_CELLS) return;
    int p    = tid / PLANE_CELLS;
    int cell = tid - p * PLANE_CELLS;
    const float* __restrict__ src = (p == 0) ? p_xy : (p == 1) ? p_yz : p_xz;

    __half2 h[8];
#pragma unroll
    for (int i = 0; i < 8; i++) {
        float a = src[(2 * i + 0) * PLANE_CELLS + cell];
        float b = src[(2 * i + 1) * PLANE_CELLS + cell];
        h[i] = __floats2half2_rn(a, b);
    }
    uint4* dst = reinterpret_cast<uint4*>(g_planes[p] + cell * NC);
    dst[0] = reinterpret_cast<const uint4*>(h)[0];
    dst[1] = reinterpret_cast<const uint4*>(h)[1];
}

__global__ __launch_bounds__(256) void transpose_lines(
    const float* __restrict__ l_x,
    const float* __restrict__ l_y,
    const float* __restrict__ l_z)
{
    int tid = blockIdx.x * blockDim.x + threadIdx.x;
    if (tid >= 3 * HW) return;
    int l = tid / HW;
    int x = tid - l * HW;
    const float* __restrict__ src = (l == 0) ? l_x : (l == 1) ? l_y : l_z;
    float4* dst = reinterpret_cast<float4*>(g_lines[l] + x * NC);
#pragma unroll
    for (int cc = 0; cc < 4; cc++) {
        float4 v;
        v.x = src[(cc * 4 + 0) * HW + x];
        v.y = src[(cc * 4 + 1) * HW + x];
        v.z = src[(cc * 4 + 2) * HW + x];
        v.w = src[(cc * 4 + 3) * HW + x];
        dst[cc] = v;
    }
}

// Load 4 consecutive fp16 plane values (8 B) and widen to fp32.
__device__ __forceinline__ float4 ldh4(const __half* __restrict__ p)
{
    uint2 u = *reinterpret_cast<const uint2*>(p);
    float2 f0 = __half22float2(*reinterpret_cast<const __half2*>(&u.x));
    float2 f1 = __half22float2(*reinterpret_cast<const __half2*>(&u.y));
    return make_float4(f0.x, f0.y, f1.x, f1.y);
}

// ---------------------------------------------------------------------------
// Main gather, cooperative 4-lane teams: 4 consecutive lanes = one (slot, n),
// lane owns channel group c = tid & 3. Plane corner = contiguous 32 B quad
// access (1 sector); line taps are fp32 64 B quad accesses (L1-resident).
//   slot 0: out_x = bilerp(plane_yz, cp[1]) * lerp(line_x, cl[0].y)
//   slot 1: out_y = bilerp(plane_xz, cp[2]) * lerp(line_y, cl[1].y)
//   slot 2: out_z = bilerp(plane_xy, cp[0]) * lerp(line_z, cl[2].y)
// ---------------------------------------------------------------------------
__global__ __launch_bounds__(256) void sample_kernel(
    const float2* __restrict__ cp,   // coords_plane, (3, N) float2
    const float2* __restrict__ cl,   // coords_line,  (3, N) float2
    float*        __restrict__ out)  // (3, N, 16)
{
    unsigned tid = blockIdx.x * blockDim.x + threadIdx.x;  // 3 * N * 4 threads
    int c    = tid & 3;                  // channel group (4 channels)
    int n    = (tid >> 2) & (NPTS - 1);  // point index
    int slot = tid >> 22;                // output slot 0..2

    // slot -> transposed plane index / cp row (line idx == slot)
    int pi = (slot == 0) ? 1 : (slot == 1) ? 2 : 0;

    float2 pc = cp[pi * NPTS + n];
    float2 lc = cl[slot * NPTS + n];

    // --- plane bilinear coords ---
    float ix = (pc.x + 1.0f) * 0.5f * (float)(HW - 1);
    float iy = (pc.y + 1.0f) * 0.5f * (float)(HW - 1);
    float ix0f = floorf(ix), iy0f = floorf(iy);
    float wx = ix - ix0f;
    float wy = iy - iy0f;
    int ix0 = min(max((int)ix0f, 0), HW - 1);
    int ix1 = min(ix0 + 1, HW - 1);
    int iy0 = min(max((int)iy0f, 0), HW - 1);
    int iy1 = min(iy0 + 1, HW - 1);

    float w00 = (1.0f - wx) * (1.0f - wy);
    float w01 = wx * (1.0f - wy);
    float w10 = (1.0f - wx) * wy;
    float w11 = wx * wy;

    const __half* __restrict__ P = g_planes[pi];
    int r0 = iy0 * (HW * NC);
    int r1 = iy1 * (HW * NC);
    int c4 = c * 4;

    float4 v00 = ldh4(P + r0 + ix0 * NC + c4);
    float4 v01 = ldh4(P + r0 + ix1 * NC + c4);
    float4 v10 = ldh4(P + r1 + ix0 * NC + c4);
    float4 v11 = ldh4(P + r1 + ix1 * NC + c4);

    // --- line linear coords (W=1 => only the y component matters) ---
    float ly = (lc.y + 1.0f) * 0.5f * (float)(HW - 1);
    float ly0f = floorf(ly);
    float wly = ly - ly0f;
    int l0 = min(max((int)ly0f, 0), HW - 1);
    int l1 = min(l0 + 1, HW - 1);
    float lw0 = 1.0f - wly;

    const float* __restrict__ L = g_lines[slot];
    float4 a0 = *reinterpret_cast<const float4*>(L + l0 * NC + c4);
    float4 a1 = *reinterpret_cast<const float4*>(L + l1 * NC + c4);

    float4 r;
    r.x = (v00.x * w00 + v01.x * w01 + v10.x * w10 + v11.x * w11)
          * (a0.x * lw0 + a1.x * wly);
    r.y = (v00.y * w00 + v01.y * w01 + v10.y * w10 + v11.y * w11)
          * (a0.y * lw0 + a1.y * wly);
    r.z = (v00.z * w00 + v01.z * w01 + v10.z * w10 + v11.z * w11)
          * (a0.z * lw0 + a1.z * wly);
    r.w = (v00.w * w00 + v01.w * w01 + v10.w * w10 + v11.w * w11)
          * (a0.w * lw0 + a1.w * wly);

    // Warp stores 8 points * 64 B = 512 B fully coalesced.
    *reinterpret_cast<float4*>(out + (size_t)slot * NPTS * NC
                                   + (size_t)n * NC + c4) = r;
}

// ---------------------------------------------------------------------------
// Inputs (metadata order):
//   0: coords_plane (3,1,N,1,2)  1: coords_line (3,1,N,1,2)
//   2: plane_xy  3: plane_yz  4: plane_xz
//   5: line_x    6: line_y    7: line_z
// Output: concat(out_x, out_y, out_z), each (N,16) f32.
// ---------------------------------------------------------------------------
extern "C" void kernel_launch(void* const* d_in, const int* in_sizes, int n_in,
                              void* d_out, int out_size)
{
    (void)in_sizes; (void)n_in; (void)out_size;

    transpose_planes<<<(3 * PLANE_CELLS + 255) / 256, 256>>>(
        (const float*)d_in[2], (const float*)d_in[3], (const float*)d_in[4]);
    transpose_lines<<<(3 * HW + 255) / 256, 256>>>(
        (const float*)d_in[5], (const float*)d_in[6], (const float*)d_in[7]);

    // 3 slots * N points * 4 lanes/point
    sample_kernel<<<(3u * NPTS * 4u) / 256, 256>>>(
        (const float2*)d_in[0], (const float2*)d_in[1], (float*)d_out);
}

// round 9
// speedup vs baseline: 2.9854x; 1.0664x over previous
#include <cuda_runtime.h>
#include <cuda_fp16.h>

// Problem constants (fixed by the reference)
#define NPTS 1048576          // N = 2^20
#define HW   300              // X = Y = Z = 300
#define NC   16               // channels
#define PLANE_CELLS (HW * HW)           // 90000
#define PLANE_ELEMS (PLANE_CELLS * NC)  // 1,440,000 elems

#define BPS 444               // blocks per slot; 3*444 = 1332 = 9 * 148 SMs
#define TPB 128               // threads per block
#define NGROUPS (NPTS / 32)   // 32768 point-groups of 32

// Channel-last scratch, fp16 (all interpolation math stays fp32).
// planes[0]=xy, [1]=yz, [2]=xz ; lines[0]=x, [1]=y, [2]=z
__device__ __align__(16) __half g_planes[3][PLANE_ELEMS];  // 8.64 MB
__device__ __align__(16) __half g_lines[3][HW * NC];       // 28.8 KB

// ---------------------------------------------------------------------------
// Transpose (C,H,W) f32 -> (H*W, C) f16.
// ---------------------------------------------------------------------------
__global__ __launch_bounds__(256) void transpose_planes(
    const float* __restrict__ p_xy,
    const float* __restrict__ p_yz,
    const float* __restrict__ p_xz)
{
    int tid = blockIdx.x * blockDim.x + threadIdx.x;
    if (tid >= 3 * PLANE_CELLS) return;
    int p    = tid / PLANE_CELLS;
    int cell = tid - p * PLANE_CELLS;
    const float* __restrict__ src = (p == 0) ? p_xy : (p == 1) ? p_yz : p_xz;

    __half2 h[8];
#pragma unroll
    for (int i = 0; i < 8; i++) {
        float a = src[(2 * i + 0) * PLANE_CELLS + cell];
        float b = src[(2 * i + 1) * PLANE_CELLS + cell];
        h[i] = __floats2half2_rn(a, b);
    }
    uint4* dst = reinterpret_cast<uint4*>(g_planes[p] + cell * NC);
    dst[0] = reinterpret_cast<const uint4*>(h)[0];
    dst[1] = reinterpret_cast<const uint4*>(h)[1];
}

__global__ __launch_bounds__(256) void transpose_lines(
    const float* __restrict__ l_x,
    const float* __restrict__ l_y,
    const float* __restrict__ l_z)
{
    int tid = blockIdx.x * blockDim.x + threadIdx.x;
    if (tid >= 3 * HW) return;
    int l = tid / HW;
    int x = tid - l * HW;
    const float* __restrict__ src = (l == 0) ? l_x : (l == 1) ? l_y : l_z;

    __half2 h[8];
#pragma unroll
    for (int i = 0; i < 8; i++) {
        h[i] = __floats2half2_rn(src[(2 * i + 0) * HW + x],
                                 src[(2 * i + 1) * HW + x]);
    }
    uint4* dst = reinterpret_cast<uint4*>(g_lines[l] + x * NC);
    dst[0] = reinterpret_cast<const uint4*>(h)[0];
    dst[1] = reinterpret_cast<const uint4*>(h)[1];
}

// Load 4 consecutive fp16 values (8 B) and widen to fp32. Works for both
// global (LDG.64) and shared (LDS.64) source pointers.
__device__ __forceinline__ float4 ldh4(const __half* p)
{
    uint2 u = *reinterpret_cast<const uint2*>(p);
    float2 f0 = __half22float2(*reinterpret_cast<const __half2*>(&u.x));
    float2 f1 = __half22float2(*reinterpret_cast<const __half2*>(&u.y));
    return make_float4(f0.x, f0.y, f1.x, f1.y);
}

// ---------------------------------------------------------------------------
// Main gather. Block-per-slot-chunk: each block copies its slot's fp16 line
// table (9.6 KB) to smem once, then grid-strides over point-groups of 32.
// Cooperative 4-lane teams: 4 consecutive lanes = one point, lane owns 4
// channels. Plane corner = contiguous 32 B quad LDG (1 L1tex wavefront);
// line taps come from smem (off the L1tex queue).
//   slot 0: out_x = bilerp(plane_yz, cp[1]) * lerp(line_x, cl[0].y)
//   slot 1: out_y = bilerp(plane_xz, cp[2]) * lerp(line_y, cl[1].y)
//   slot 2: out_z = bilerp(plane_xy, cp[0]) * lerp(line_z, cl[2].y)
// ---------------------------------------------------------------------------
__global__ __launch_bounds__(TPB, 9) void sample_kernel(
    const float2* __restrict__ cp,   // coords_plane, (3, N) float2
    const float2* __restrict__ cl,   // coords_line,  (3, N) float2
    float*        __restrict__ out)  // (3, N, 16)
{
    __shared__ __align__(16) __half s_line[HW * NC];   // 9.6 KB

    int slot = blockIdx.x / BPS;
    int blk  = blockIdx.x - slot * BPS;
    int pi   = (slot == 0) ? 1 : (slot == 1) ? 2 : 0;  // transposed plane idx

    // Copy this slot's line table into smem (600 x uint4).
    {
        const uint4* __restrict__ src = reinterpret_cast<const uint4*>(g_lines[slot]);
        uint4* dst = reinterpret_cast<uint4*>(s_line);
        for (int i = threadIdx.x; i < (HW * NC) / 8; i += TPB)
            dst[i] = src[i];
    }
    __syncthreads();

    const __half* __restrict__ P = g_planes[pi];
    const float2* __restrict__ CP = cp + pi * NPTS;
    const float2* __restrict__ CL = cl + slot * NPTS;
    float* __restrict__ O = out + (size_t)slot * NPTS * NC;

    int c     = threadIdx.x & 3;        // channel group
    int c4    = c * 4;
    int pofs  = threadIdx.x >> 2;       // 0..31 point within group

    for (int g = blk; g < NGROUPS; g += BPS) {
        int n = g * 32 + pofs;

        float2 pc = CP[n];
        float2 lc = CL[n];

        // --- plane bilinear ---
        float ix = (pc.x + 1.0f) * 0.5f * (float)(HW - 1);
        float iy = (pc.y + 1.0f) * 0.5f * (float)(HW - 1);
        float ix0f = floorf(ix), iy0f = floorf(iy);
        float wx = ix - ix0f;
        float wy = iy - iy0f;
        int ix0 = min(max((int)ix0f, 0), HW - 1);
        int ix1 = min(ix0 + 1, HW - 1);
        int iy0 = min(max((int)iy0f, 0), HW - 1);
        int iy1 = min(iy0 + 1, HW - 1);

        float w00 = (1.0f - wx) * (1.0f - wy);
        float w01 = wx * (1.0f - wy);
        float w10 = (1.0f - wx) * wy;
        float w11 = wx * wy;

        int r0 = iy0 * (HW * NC);
        int r1 = iy1 * (HW * NC);

        float4 v00 = ldh4(P + r0 + ix0 * NC + c4);
        float4 v01 = ldh4(P + r0 + ix1 * NC + c4);
        float4 v10 = ldh4(P + r1 + ix0 * NC + c4);
        float4 v11 = ldh4(P + r1 + ix1 * NC + c4);

        // --- line linear (W=1 => only y component) from smem ---
        float ly = (lc.y + 1.0f) * 0.5f * (float)(HW - 1);
        float ly0f = floorf(ly);
        float wly = ly - ly0f;
        int l0 = min(max((int)ly0f, 0), HW - 1);
        int l1 = min(l0 + 1, HW - 1);
        float lw0 = 1.0f - wly;

        float4 a0 = ldh4(s_line + l0 * NC + c4);
        float4 a1 = ldh4(s_line + l1 * NC + c4);

        float4 r;
        r.x = (v00.x * w00 + v01.x * w01 + v10.x * w10 + v11.x * w11)
              * (a0.x * lw0 + a1.x * wly);
        r.y = (v00.y * w00 + v01.y * w01 + v10.y * w10 + v11.y * w11)
              * (a0.y * lw0 + a1.y * wly);
        r.z = (v00.z * w00 + v01.z * w01 + v10.z * w10 + v11.z * w11)
              * (a0.z * lw0 + a1.z * wly);
        r.w = (v00.w * w00 + v01.w * w01 + v10.w * w10 + v11.w * w11)
              * (a0.w * lw0 + a1.w * wly);

        // Warp stores 8 points * 64 B = 512 B fully coalesced.
        *reinterpret_cast<float4*>(O + (size_t)n * NC + c4) = r;
    }
}

// ---------------------------------------------------------------------------
// Inputs (metadata order):
//   0: coords_plane (3,1,N,1,2)  1: coords_line (3,1,N,1,2)
//   2: plane_xy  3: plane_yz  4: plane_xz
//   5: line_x    6: line_y    7: line_z
// Output: concat(out_x, out_y, out_z), each (N,16) f32.
// ---------------------------------------------------------------------------
extern "C" void kernel_launch(void* const* d_in, const int* in_sizes, int n_in,
                              void* d_out, int out_size)
{
    (void)in_sizes; (void)n_in; (void)out_size;

    transpose_planes<<<(3 * PLANE_CELLS + 255) / 256, 256>>>(
        (const float*)d_in[2], (const float*)d_in[3], (const float*)d_in[4]);
    transpose_lines<<<(3 * HW + 255) / 256, 256>>>(
        (const float*)d_in[5], (const float*)d_in[6], (const float*)d_in[7]);

    sample_kernel<<<3 * BPS, TPB>>>(
        (const float2*)d_in[0], (const float2*)d_in[1], (float*)d_out);
}